// round 1
// baseline (speedup 1.0000x reference)
#include <cuda_runtime.h>

#define NPTS   50000
#define KNN    16
#define CH     128
#define CSH    16
#define MROWS  (NPTS*KNN)
#define BN_EPS 1e-5f

// ---------------- device scratch (no allocations allowed) ----------------
__device__ __align__(16) float g_z[NPTS*CSH];
__device__ __align__(16) float g_num[NPTS*CSH];
__device__ float g_stats[6];   // [0..2] sum(h), [3..5] sum(h^2)
__device__ float g_M[3*CSH];   // folded p-path matrix (3 x 16)
__device__ float g_Bc[CSH];    // folded bias for s
__device__ float g_wf[9];      // BN-folded W_p1 (gamma*rstd absorbed)
__device__ float g_gb[3];      // BN shift (beta - mu*scale)

// ---------------- init: zero accumulators ----------------
__global__ void init_kernel() {
    int i = blockIdx.x*blockDim.x + threadIdx.x;
    if (i < NPTS*CSH) { g_z[i] = 0.f; g_num[i] = 0.f; }
    if (i < 6) g_stats[i] = 0.f;
}

// ---------------- BN stats over h = p_r @ W_p1^T ----------------
__global__ void stats_kernel(const float* __restrict__ p_r,
                             const float* __restrict__ W_p1) {
    float w0=W_p1[0],w1=W_p1[1],w2=W_p1[2],w3=W_p1[3],w4=W_p1[4],
          w5=W_p1[5],w6=W_p1[6],w7=W_p1[7],w8=W_p1[8];
    float s0=0,s1=0,s2=0,q0=0,q1=0,q2=0;
    int stride = gridDim.x*blockDim.x;
    for (int i = blockIdx.x*blockDim.x + threadIdx.x; i < MROWS; i += stride) {
        float p0=p_r[3*i+0], p1=p_r[3*i+1], p2=p_r[3*i+2];
        float h0 = p0*w0 + p1*w1 + p2*w2;
        float h1 = p0*w3 + p1*w4 + p2*w5;
        float h2 = p0*w6 + p1*w7 + p2*w8;
        s0+=h0; q0+=h0*h0; s1+=h1; q1+=h1*h1; s2+=h2; q2+=h2*h2;
    }
    #pragma unroll
    for (int o=16;o>0;o>>=1){
        s0+=__shfl_down_sync(0xffffffffu,s0,o);
        s1+=__shfl_down_sync(0xffffffffu,s1,o);
        s2+=__shfl_down_sync(0xffffffffu,s2,o);
        q0+=__shfl_down_sync(0xffffffffu,q0,o);
        q1+=__shfl_down_sync(0xffffffffu,q1,o);
        q2+=__shfl_down_sync(0xffffffffu,q2,o);
    }
    __shared__ float red[8][6];
    int wid = threadIdx.x>>5, lid = threadIdx.x&31;
    if (lid==0){ red[wid][0]=s0; red[wid][1]=s1; red[wid][2]=s2;
                 red[wid][3]=q0; red[wid][4]=q1; red[wid][5]=q2; }
    __syncthreads();
    if (threadIdx.x < 6) {
        float a = 0.f;
        #pragma unroll
        for (int w=0; w<8; w++) a += red[w][threadIdx.x];
        atomicAdd(&g_stats[threadIdx.x], a);
    }
}

// ---------------- fold constants: BN, M = W_p2^T @ W_lin_p^T, biases ----------------
__global__ void consts_kernel(const float* __restrict__ W_lin,
                              const float* __restrict__ b_lin,
                              const float* __restrict__ W_p2,
                              const float* __restrict__ b_p2,
                              const float* __restrict__ W_p1,
                              const float* __restrict__ gamma,
                              const float* __restrict__ beta) {
    int tid = threadIdx.x;
    if (tid < 3) {
        float inv = 1.f / (float)MROWS;
        float mu  = g_stats[tid] * inv;
        float var = g_stats[3+tid] * inv - mu*mu;
        float gs  = gamma[tid] * rsqrtf(var + BN_EPS);
        g_gb[tid] = beta[tid] - mu*gs;
        #pragma unroll
        for (int c=0;c<3;c++) g_wf[tid*3+c] = gs * W_p1[tid*3+c];
    }
    if (tid < 48) {
        int a = tid >> 4, j = tid & 15;
        float m = 0.f;
        for (int c=0;c<CH;c++) m += W_p2[c*3+a] * W_lin[j*256+c];
        g_M[a*CSH + j] = m;
    }
    if (tid >= 48 && tid < 64) {
        int j = tid - 48;
        float b = b_lin[j];
        for (int c=0;c<CH;c++) b += b_p2[c] * W_lin[j*256+c];
        g_Bc[j] = b;
    }
}

// ---------------- fused main kernel ----------------
struct SmemT {
    float As[128][132];   // x_knn tile, padded (row stride 132 floats)
    float Bs[128][36];    // weights k-major: col<16 -> W_lin[:,128:], col>=16 -> W_x
    float es[128][16];    // exp(s) exchange
    float hs[128][4];     // BN'd relu'd h per row
    int   is[128];        // segment index per row
    float Ms[3][16];
    float Bc[16];
    float bx[16];
    float wf[12];
    float gb[4];
};

__global__ void __launch_bounds__(128, 2) main_kernel(
    const float* __restrict__ x_knn,
    const int*   __restrict__ knn_idx,
    const float* __restrict__ p_r,
    const float* __restrict__ W_lin,
    const float* __restrict__ W_x,
    const float* __restrict__ b_x)
{
    extern __shared__ char smem_raw[];
    SmemT& sm = *reinterpret_cast<SmemT*>(smem_raw);
    const int tid  = threadIdx.x;
    const int base = blockIdx.x * 128;

    // stage A tile (coalesced float4)
    const float4* src = reinterpret_cast<const float4*>(x_knn) + (size_t)base * 32;
    #pragma unroll
    for (int i=0;i<32;i++){
        int q = i*128 + tid;
        float4 v = src[q];
        *reinterpret_cast<float4*>(&sm.As[q>>5][(q&31)*4]) = v;
    }
    // stage B weights k-major
    #pragma unroll
    for (int i=0;i<32;i++){
        int q = i*128 + tid;
        int col = q>>7, k = q&127;
        sm.Bs[k][col] = (col < CSH) ? W_lin[col*256 + 128 + k]
                                    : W_x[(col-CSH)*CH + k];
    }
    if (tid < 48)       sm.Ms[tid>>4][tid&15] = g_M[tid];
    else if (tid < 64)  sm.Bc[tid-48] = g_Bc[tid-48];
    else if (tid < 80)  sm.bx[tid-64] = b_x[tid-64];
    else if (tid < 89)  sm.wf[tid-80] = g_wf[tid-80];
    else if (tid < 92)  sm.gb[tid-89] = g_gb[tid-89];
    sm.is[tid] = knn_idx[base + tid];
    __syncthreads();

    // per-row BN'd relu'd h (3 values)
    {
        int r = base + tid;
        float p0 = p_r[3*r+0], p1 = p_r[3*r+1], p2 = p_r[3*r+2];
        #pragma unroll
        for (int a=0;a<3;a++){
            float h = p0*sm.wf[a*3+0] + p1*sm.wf[a*3+1] + p2*sm.wf[a*3+2] + sm.gb[a];
            sm.hs[tid][a] = fmaxf(h, 0.f);
        }
    }
    __syncthreads();

    // register-tiled GEMM: C[128 x 32] = A[128 x 128] * B[128 x 32], f32x2 packed
    const int cg = tid & 3;    // col group: 8 cols each (0,1 -> s; 2,3 -> v)
    const int rg = tid >> 2;   // row group: rows rg + 32*r
    unsigned long long acc[4][4];
    #pragma unroll
    for (int r=0;r<4;r++)
        #pragma unroll
        for (int c=0;c<4;c++) acc[r][c] = 0ull;

    #pragma unroll 4
    for (int k4=0;k4<32;k4++){
        float4 av[4];
        #pragma unroll
        for (int r=0;r<4;r++)
            av[r] = *reinterpret_cast<const float4*>(&sm.As[rg + 32*r][k4*4]);
        #pragma unroll
        for (int kk=0;kk<4;kk++){
            ulonglong2 b01 = *reinterpret_cast<const ulonglong2*>(&sm.Bs[k4*4+kk][8*cg]);
            ulonglong2 b23 = *reinterpret_cast<const ulonglong2*>(&sm.Bs[k4*4+kk][8*cg+4]);
            #pragma unroll
            for (int r=0;r<4;r++){
                float a = (kk==0) ? av[r].x : (kk==1) ? av[r].y : (kk==2) ? av[r].z : av[r].w;
                unsigned long long aa;
                asm("mov.b64 %0, {%1, %1};" : "=l"(aa) : "r"(__float_as_uint(a)));
                asm("fma.rn.f32x2 %0, %1, %2, %0;" : "+l"(acc[r][0]) : "l"(aa), "l"(b01.x));
                asm("fma.rn.f32x2 %0, %1, %2, %0;" : "+l"(acc[r][1]) : "l"(aa), "l"(b01.y));
                asm("fma.rn.f32x2 %0, %1, %2, %0;" : "+l"(acc[r][2]) : "l"(aa), "l"(b23.x));
                asm("fma.rn.f32x2 %0, %1, %2, %0;" : "+l"(acc[r][3]) : "l"(aa), "l"(b23.y));
            }
        }
    }

    float out2[4][8];
    #pragma unroll
    for (int r=0;r<4;r++)
        #pragma unroll
        for (int c=0;c<4;c++){
            out2[r][2*c]   = __uint_as_float((unsigned)(acc[r][c] & 0xffffffffull));
            out2[r][2*c+1] = __uint_as_float((unsigned)(acc[r][c] >> 32));
        }

    // epilogue: s-threads produce e=exp(relu(s)) and scatter z; v-threads scatter num
    if (cg < 2) {
        const int jb = 8*cg;
        #pragma unroll
        for (int r=0;r<4;r++){
            int row = rg + 32*r;
            float h0 = sm.hs[row][0], h1 = sm.hs[row][1], h2 = sm.hs[row][2];
            float e[8];
            #pragma unroll
            for (int c=0;c<8;c++){
                int j = jb + c;
                float sv = out2[r][c] + sm.Bc[j]
                         + h0*sm.Ms[0][j] + h1*sm.Ms[1][j] + h2*sm.Ms[2][j];
                e[c] = __expf(fmaxf(sv, 0.f));
                sm.es[row][j] = e[c];
            }
            float* zp = &g_z[sm.is[row]*CSH + jb];
            asm volatile("red.global.add.v4.f32 [%0], {%1,%2,%3,%4};"
                         :: "l"(zp),   "f"(e[0]), "f"(e[1]), "f"(e[2]), "f"(e[3]) : "memory");
            asm volatile("red.global.add.v4.f32 [%0], {%1,%2,%3,%4};"
                         :: "l"(zp+4), "f"(e[4]), "f"(e[5]), "f"(e[6]), "f"(e[7]) : "memory");
        }
    } else {
        const int jb = 8*(cg-2);
        #pragma unroll
        for (int r=0;r<4;r++)
            #pragma unroll
            for (int c=0;c<8;c++)
                out2[r][c] = fmaxf(out2[r][c] + sm.bx[jb+c], 0.f);
    }
    __syncthreads();
    if (cg >= 2) {
        const int jb = 8*(cg-2);
        #pragma unroll
        for (int r=0;r<4;r++){
            int row = rg + 32*r;
            float w[8];
            #pragma unroll
            for (int c=0;c<8;c++) w[c] = out2[r][c] * sm.es[row][jb+c];
            float* np = &g_num[sm.is[row]*CSH + jb];
            asm volatile("red.global.add.v4.f32 [%0], {%1,%2,%3,%4};"
                         :: "l"(np),   "f"(w[0]), "f"(w[1]), "f"(w[2]), "f"(w[3]) : "memory");
            asm volatile("red.global.add.v4.f32 [%0], {%1,%2,%3,%4};"
                         :: "l"(np+4), "f"(w[4]), "f"(w[5]), "f"(w[6]), "f"(w[7]) : "memory");
        }
    }
}

// ---------------- output: x + tile(num/z, 8) ----------------
__global__ void out_kernel(const float* __restrict__ x, float* __restrict__ out) {
    int i = blockIdx.x*blockDim.x + threadIdx.x;
    if (i >= NPTS*32) return;
    int n = i >> 5, q = i & 31;
    int jb = (q & 3) * 4;               // (4q) % 16
    float4 xv = reinterpret_cast<const float4*>(x)[i];
    float4 zv = *reinterpret_cast<const float4*>(&g_z[n*CSH + jb]);
    float4 nv = *reinterpret_cast<const float4*>(&g_num[n*CSH + jb]);
    float4 o;
    o.x = xv.x + (zv.x > 0.f ? nv.x / zv.x : 0.f);
    o.y = xv.y + (zv.y > 0.f ? nv.y / zv.y : 0.f);
    o.z = xv.z + (zv.z > 0.f ? nv.z / zv.z : 0.f);
    o.w = xv.w + (zv.w > 0.f ? nv.w / zv.w : 0.f);
    reinterpret_cast<float4*>(out)[i] = o;
}

// ---------------- launch ----------------
extern "C" void kernel_launch(void* const* d_in, const int* in_sizes, int n_in,
                              void* d_out, int out_size) {
    (void)in_sizes; (void)n_in; (void)out_size;
    const float* x       = (const float*)d_in[0];
    const float* x_knn   = (const float*)d_in[1];
    const int*   knn_idx = (const int*)  d_in[2];
    const float* p_r     = (const float*)d_in[3];
    const float* W_lin   = (const float*)d_in[4];
    const float* b_lin   = (const float*)d_in[5];
    const float* W_x     = (const float*)d_in[6];
    const float* b_x     = (const float*)d_in[7];
    const float* W_p1    = (const float*)d_in[8];
    const float* gamma   = (const float*)d_in[9];
    const float* beta    = (const float*)d_in[10];
    const float* W_p2    = (const float*)d_in[11];
    const float* b_p2    = (const float*)d_in[12];

    cudaFuncSetAttribute(main_kernel, cudaFuncAttributeMaxDynamicSharedMemorySize,
                         (int)sizeof(SmemT));

    init_kernel<<<(NPTS*CSH + 255)/256, 256>>>();
    stats_kernel<<<592, 256>>>(p_r, W_p1);
    consts_kernel<<<1, 64>>>(W_lin, b_lin, W_p2, b_p2, W_p1, gamma, beta);
    main_kernel<<<MROWS/128, 128, sizeof(SmemT)>>>(x_knn, knn_idx, p_r, W_lin, W_x, b_x);
    out_kernel<<<(NPTS*32 + 255)/256, 256>>>(x, (float*)d_out);
}